// round 16
// baseline (speedup 1.0000x reference)
#include <cuda_runtime.h>
#include <cuda_bf16.h>
#include <cstdint>

#define MDIM 65536      // 4*128*128 input pixels
#define KDIM 256        // input channels
#define NDIM 2304       // 9 taps * 256 out channels

__device__ float g_z[(size_t)MDIM * NDIM];                 // z = x @ B^T (604 MB)
__device__ __nv_bfloat16 g_Bhi[(size_t)NDIM * KDIM];
__device__ __nv_bfloat16 g_Blo[(size_t)NDIM * KDIM];
__device__ __nv_bfloat16 g_xhi[(size_t)MDIM * KDIM];
__device__ __nv_bfloat16 g_xlo[(size_t)MDIM * KDIM];

__device__ __forceinline__ uint32_t smem_to_u32(const void* p) {
    uint32_t a;
    asm("{ .reg .u64 t; cvta.to.shared.u64 t, %1; cvt.u32.u64 %0, t; }" : "=r"(a) : "l"(p));
    return a;
}
__device__ __forceinline__ void cp_async16(uint32_t dst, const void* src) {
    asm volatile("cp.async.cg.shared.global [%0], [%1], 16;"
                 :: "r"(dst), "l"(__cvta_generic_to_global(src)));
}
// 16B copy with zero-fill when srcsz == 0 (ignore-src form)
__device__ __forceinline__ void cp_async16_z(uint32_t dst, const void* src, uint32_t srcsz) {
    asm volatile("cp.async.cg.shared.global [%0], [%1], 16, %2;"
                 :: "r"(dst), "l"(__cvta_generic_to_global(src)), "r"(srcsz));
}
#define CP_COMMIT() asm volatile("cp.async.commit_group;" ::: "memory")
#define CP_WAIT(N)  asm volatile("cp.async.wait_group %0;" :: "n"(N) : "memory")

#define LDMATRIX_X4(r0, r1, r2, r3, addr) \
    asm volatile("ldmatrix.sync.aligned.m8n8.x4.shared.b16 {%0,%1,%2,%3}, [%4];" \
                 : "=r"(r0), "=r"(r1), "=r"(r2), "=r"(r3) : "r"(addr))

__device__ __forceinline__ void mma16816(float* d, const uint32_t* a,
                                         uint32_t b0, uint32_t b1) {
    asm volatile(
        "mma.sync.aligned.m16n8k16.row.col.f32.bf16.bf16.f32 "
        "{%0,%1,%2,%3}, {%4,%5,%6,%7}, {%8,%9}, {%0,%1,%2,%3};"
        : "+f"(d[0]), "+f"(d[1]), "+f"(d[2]), "+f"(d[3])
        : "r"(a[0]), "r"(a[1]), "r"(a[2]), "r"(a[3]), "r"(b0), "r"(b1));
}

// FIR/phase coefficients A[r][jn][t], jn=j+1; l-index offset uses (2-jn).
__device__ constexpr float AT[2][3][3] = {
    { {0.00f, 0.00f, 0.25f},
      {0.25f, 0.75f, 0.75f},
      {0.75f, 0.25f, 0.00f} },
    { {0.00f, 0.25f, 0.75f},
      {0.75f, 0.75f, 0.25f},
      {0.25f, 0.00f, 0.00f} }
};

// ---------------------------------------------------------------------------
// Kernel 1a / 1b: bf16 hi/lo splits
// ---------------------------------------------------------------------------
__global__ void prep_w_kernel(const float* __restrict__ w) {
    int o = blockIdx.x * 256 + threadIdx.x;
    int n  = o >> 8;
    int ci = o & 255;
    int tt = n >> 8;
    int co = n & 255;
    float v = w[(tt * 256 + ci) * 256 + co];
    __nv_bfloat16 h = __float2bfloat16_rn(v);
    float rem = v - __bfloat162float(h);
    g_Bhi[(size_t)n * KDIM + ci] = h;
    g_Blo[(size_t)n * KDIM + ci] = __float2bfloat16_rn(rem);
}

__global__ void prep_x_kernel(const float* __restrict__ x) {
    size_t i = ((size_t)blockIdx.x * 256 + threadIdx.x) * 4;
    const float4 v = *(const float4*)(x + i);
    __nv_bfloat162 h01 = __floats2bfloat162_rn(v.x, v.y);
    __nv_bfloat162 h23 = __floats2bfloat162_rn(v.z, v.w);
    float2 f01 = __bfloat1622float2(h01);
    float2 f23 = __bfloat1622float2(h23);
    __nv_bfloat162 l01 = __floats2bfloat162_rn(v.x - f01.x, v.y - f01.y);
    __nv_bfloat162 l23 = __floats2bfloat162_rn(v.z - f23.x, v.w - f23.y);
    *(uint2*)&g_xhi[i] = make_uint2(*(uint32_t*)&h01, *(uint32_t*)&h23);
    *(uint2*)&g_xlo[i] = make_uint2(*(uint32_t*)&l01, *(uint32_t*)&l23);
}

// ---------------------------------------------------------------------------
// Kernel 2: GEMM v3 — operand-reuse 3-pass with RAW-free accumulator order.
// BM=256, BN=128, 4 chunks of K=64; per chunk stage {Ahi,Alo,Bhi,Blo} once.
// Each pass sweeps all 16 accumulators before any is reused (hides HMMA lat).
// 512 threads (8m x 2n warps, 32x64 tile), 2-stage cp.async, 1 CTA/SM.
// ---------------------------------------------------------------------------
#define LDSR 72
#define S_AHI 0
#define S_ALO 18432
#define S_BHI 36864
#define S_BLO 46080
#define STAGE_ELEMS 55296
#define GSMEM_BYTES (2 * STAGE_ELEMS * 2)   // 221184

__global__ __launch_bounds__(512, 1) void gemm_kernel() {
    extern __shared__ __nv_bfloat16 smem[];
    const uint32_t sb = smem_to_u32(smem);
    const int tid = threadIdx.x;
    const int lane = tid & 31;
    const int wid = tid >> 5;
    const int n0 = blockIdx.x * 128;
    const int m0 = blockIdx.y * 256;
    const int wm = (wid >> 1) * 32;          // 0..224
    const int wn = (wid & 1) * 64;

    auto load_chunk = [&](int stage, int kk) {
        const uint32_t base = sb + (uint32_t)(stage * STAGE_ELEMS * 2);
#pragma unroll
        for (int i = 0; i < 12; i++) {
            int c = i * 512 + tid;
            if (i < 8) {
                int t  = c >> 11;                 // 0 = hi, 1 = lo
                int r  = (c >> 3) & 255;
                int c8 = c & 7;
                const __nv_bfloat16* src = (t ? g_xlo : g_xhi)
                                         + (size_t)(m0 + r) * KDIM + kk + c8 * 8;
                uint32_t dst = base + (uint32_t)(((t ? S_ALO : S_AHI)
                                         + r * LDSR + c8 * 8) * 2);
                cp_async16(dst, src);
            } else {
                int cc = c - 4096;
                int t  = cc >> 10;                // 0 = hi, 1 = lo
                int r  = (cc >> 3) & 127;
                int c8 = cc & 7;
                const __nv_bfloat16* src = (t ? g_Blo : g_Bhi)
                                         + (size_t)(n0 + r) * KDIM + kk + c8 * 8;
                uint32_t dst = base + (uint32_t)(((t ? S_BLO : S_BHI)
                                         + r * LDSR + c8 * 8) * 2);
                cp_async16(dst, src);
            }
        }
        CP_COMMIT();
    };

    float d[2][8][4];
#pragma unroll
    for (int i = 0; i < 2; i++)
#pragma unroll
        for (int j = 0; j < 8; j++)
#pragma unroll
            for (int q = 0; q < 4; q++) d[i][j][q] = 0.f;

    const int ar = (lane & 7) + ((lane >> 3) & 1) * 8;
    const int ac = (lane >> 4) * 8;
    const int br = (lane & 7) + ((lane >> 4) & 1) * 8;
    const int bc = ((lane >> 3) & 1) * 8;

    load_chunk(0, 0);

    for (int ch = 0; ch < 4; ch++) {
        CP_WAIT(0);
        __syncthreads();
        if (ch < 3) load_chunk((ch + 1) & 1, (ch + 1) * 64);

        const uint32_t st = sb + (uint32_t)((ch & 1) * STAGE_ELEMS * 2);
#pragma unroll
        for (int k16 = 0; k16 < 4; k16++) {
            const int kc = k16 * 16;
            uint32_t ah[2][4], al[2][4], bh[4][4], bl[4][4];
#pragma unroll
            for (int mt = 0; mt < 2; mt++) {
                int r = wm + mt * 16 + ar;
                int c = kc + ac;
                LDMATRIX_X4(ah[mt][0], ah[mt][1], ah[mt][2], ah[mt][3],
                            st + (uint32_t)((S_AHI + r * LDSR + c) * 2));
                LDMATRIX_X4(al[mt][0], al[mt][1], al[mt][2], al[mt][3],
                            st + (uint32_t)((S_ALO + r * LDSR + c) * 2));
            }
#pragma unroll
            for (int nt = 0; nt < 4; nt++) {
                int rb = wn + nt * 16 + br;
                int cb = kc + bc;
                LDMATRIX_X4(bh[nt][0], bh[nt][1], bh[nt][2], bh[nt][3],
                            st + (uint32_t)((S_BHI + rb * LDSR + cb) * 2));
            }
            // pass 1: ahi*bhi — all 16 accumulators, no back-to-back reuse
#pragma unroll
            for (int mt = 0; mt < 2; mt++)
#pragma unroll
                for (int nt = 0; nt < 4; nt++)
#pragma unroll
                    for (int h = 0; h < 2; h++)
                        mma16816(d[mt][nt * 2 + h], ah[mt], bh[nt][h * 2], bh[nt][h * 2 + 1]);
            // pass 2: alo*bhi — d[i] reused only after 15 intervening HMMAs
#pragma unroll
            for (int mt = 0; mt < 2; mt++)
#pragma unroll
                for (int nt = 0; nt < 4; nt++)
#pragma unroll
                    for (int h = 0; h < 2; h++)
                        mma16816(d[mt][nt * 2 + h], al[mt], bh[nt][h * 2], bh[nt][h * 2 + 1]);
            // pass 3: ahi*blo — bl LDSM latency hidden under pass 2
#pragma unroll
            for (int nt = 0; nt < 4; nt++) {
                int rb = wn + nt * 16 + br;
                int cb = kc + bc;
                LDMATRIX_X4(bl[nt][0], bl[nt][1], bl[nt][2], bl[nt][3],
                            st + (uint32_t)((S_BLO + rb * LDSR + cb) * 2));
            }
#pragma unroll
            for (int mt = 0; mt < 2; mt++)
#pragma unroll
                for (int nt = 0; nt < 4; nt++)
#pragma unroll
                    for (int h = 0; h < 2; h++)
                        mma16816(d[mt][nt * 2 + h], ah[mt], bl[nt][h * 2], bl[nt][h * 2 + 1]);
        }
    }

#pragma unroll
    for (int mt = 0; mt < 2; mt++) {
        const int mrow = m0 + wm + mt * 16 + (lane >> 2);
#pragma unroll
        for (int j = 0; j < 8; j++) {
            const int ncol = n0 + wn + (j >> 1) * 16 + (j & 1) * 8 + (lane & 3) * 2;
            float* p0 = g_z + (size_t)mrow * NDIM + ncol;
            float* p1 = g_z + (size_t)(mrow + 8) * NDIM + ncol;
            *(float2*)p0 = make_float2(d[mt][j][0], d[mt][j][1]);
            *(float2*)p1 = make_float2(d[mt][j][2], d[mt][j][3]);
        }
    }
}

// ---------------------------------------------------------------------------
// Kernel 3: combine v4 — separable, l1-slice streamed, 2 CTAs/SM. (unchanged)
// ---------------------------------------------------------------------------
#define SS_FLOATS 15360
#define ZB_FLOATS (4 * 2880)
#define CSMEM_BYTES ((SS_FLOATS + ZB_FLOATS) * 4)   // 107520

__global__ __launch_bounds__(512) void combine_kernel(const float* __restrict__ bias,
                                                      float* __restrict__ out) {
    extern __shared__ float ss[];            // [10][8][6][32]
    float* zb = ss + SS_FLOATS;              // [4][90][32]
    const uint32_t zbb = smem_to_u32(zb);

    const int co0 = blockIdx.x * 32;
    const int T2  = blockIdx.y;
    const int bz  = blockIdx.z;
    const int b   = bz >> 4;
    const int T1  = bz & 15;
    const int u10 = T1 * 8, u20 = T2 * 8;
    const int tid = threadIdx.x;
    const int lane = tid & 31;
    const int warp = tid >> 5;

    auto load_pair = [&](int j) {
        const int sub = tid >> 3;
        const int qo  = (tid & 7) * 4;
#pragma unroll
        for (int pass = 0; pass < 3; pass++) {
            int c = pass * 64 + sub;
            if (c < 180) {
                int sl = (c >= 90) ? 1 : 0;
                int rem = c - sl * 90;
                int l2 = rem / 9;
                int t  = rem - l2 * 9;
                int l1 = 2 * j + sl;
                int u1 = u10 + l1 - 1;
                int u2 = u20 + l2 - 1;
                bool ok = ((unsigned)u1 < 128u) && ((unsigned)u2 < 128u);
                int cu1 = ok ? u1 : 0, cu2 = ok ? u2 : 0;
                const float* src = g_z + (size_t)((b * 128 + cu1) * 128 + cu2) * NDIM
                                       + t * 256 + co0 + qo;
                int slot = (2 * j + sl) & 3;
                cp_async16_z(zbb + (uint32_t)((slot * 90 + l2 * 9 + t) * 32 + qo) * 4,
                             src, ok ? 16u : 0u);
            }
        }
        CP_COMMIT();
    };

    load_pair(0);
    load_pair(1);

    const int p  = warp >> 3;
    const int c2 = warp & 7;

    for (int i = 0; i < 5; i++) {
        if (i < 4) { CP_WAIT(1); } else { CP_WAIT(0); }
        __syncthreads();

        {
            const int l1 = 2 * i + p;
            const float* zsl = zb + ((2 * i + p) & 3) * 2880;
            const float* zrow = zsl + c2 * 288 + lane;
            float acc[2][3] = {{0.f, 0.f, 0.f}, {0.f, 0.f, 0.f}};
#pragma unroll
            for (int jn = 0; jn < 3; jn++) {
                const int l2off = (2 - jn) * 288;
#pragma unroll
                for (int t2 = 0; t2 < 3; t2++) {
                    const float c0  = AT[0][jn][t2];
                    const float c1v = AT[1][jn][t2];
                    if (c0 == 0.f && c1v == 0.f) continue;
                    float zv0 = zrow[l2off + (0 * 3 + t2) * 32];
                    float zv1 = zrow[l2off + (1 * 3 + t2) * 32];
                    float zv2 = zrow[l2off + (2 * 3 + t2) * 32];
                    if (c0 != 0.f) {
                        acc[0][0] = fmaf(c0, zv0, acc[0][0]);
                        acc[0][1] = fmaf(c0, zv1, acc[0][1]);
                        acc[0][2] = fmaf(c0, zv2, acc[0][2]);
                    }
                    if (c1v != 0.f) {
                        acc[1][0] = fmaf(c1v, zv0, acc[1][0]);
                        acc[1][1] = fmaf(c1v, zv1, acc[1][1]);
                        acc[1][2] = fmaf(c1v, zv2, acc[1][2]);
                    }
                }
            }
            float* sp = ss + ((l1 * 8 + c2) * 6) * 32 + lane;
#pragma unroll
            for (int r2 = 0; r2 < 2; r2++)
#pragma unroll
                for (int t1 = 0; t1 < 3; t1++)
                    sp[(r2 * 3 + t1) * 32] = acc[r2][t1];
        }
        __syncthreads();
        if (i + 2 < 5) load_pair(i + 2);
    }

    const float bv = bias[co0 + lane];
#pragma unroll
    for (int i = 0; i < 4; i++) {
        const int g = warp + 16 * i;
        const int c1 = g >> 3;
        const int c2b = g & 7;
        const float* sp = ss + ((c1 * 8 + c2b) * 6) * 32 + lane;
        float o00 = 0.f, o01 = 0.f, o10 = 0.f, o11 = 0.f;
#pragma unroll
        for (int jn = 0; jn < 3; jn++) {
            const int l1off = (2 - jn) * 1536;
#pragma unroll
            for (int t1 = 0; t1 < 3; t1++) {
                const float c0  = AT[0][jn][t1];
                const float c1v = AT[1][jn][t1];
                if (c0 == 0.f && c1v == 0.f) continue;
                float s0 = sp[l1off + (0 * 3 + t1) * 32];
                float s1 = sp[l1off + (1 * 3 + t1) * 32];
                if (c0 != 0.f)  { o00 = fmaf(c0,  s0, o00); o01 = fmaf(c0,  s1, o01); }
                if (c1v != 0.f) { o10 = fmaf(c1v, s0, o10); o11 = fmaf(c1v, s1, o11); }
            }
        }
        const int o1 = 2 * (u10 + c1);
        const int o2 = 2 * (u20 + c2b);
        float* pp = out + (((size_t)(b * 256 + o1)) * 256 + o2) * 256 + co0 + lane;
        pp[0]           = o00 + bv;
        pp[256]         = o01 + bv;
        pp[65536]       = o10 + bv;
        pp[65536 + 256] = o11 + bv;
    }
}

// ---------------------------------------------------------------------------
extern "C" void kernel_launch(void* const* d_in, const int* in_sizes, int n_in,
                              void* d_out, int out_size) {
    const float* x = (const float*)d_in[0];   // [4,128,128,256]
    const float* w = (const float*)d_in[1];   // [3,3,256,256]
    const float* b = (const float*)d_in[2];   // [256]
    float* out = (float*)d_out;               // [4,256,256,256]

    prep_w_kernel<<<2304, 256>>>(w);
    prep_x_kernel<<<16384, 256>>>(x);

    cudaFuncSetAttribute(gemm_kernel,
                         cudaFuncAttributeMaxDynamicSharedMemorySize, GSMEM_BYTES);
    dim3 ggrid(NDIM / 128, MDIM / 256);       // (18, 256)
    gemm_kernel<<<ggrid, 512, GSMEM_BYTES>>>();

    cudaFuncSetAttribute(combine_kernel,
                         cudaFuncAttributeMaxDynamicSharedMemorySize, CSMEM_BYTES);
    dim3 cgrid(8, 16, 64);
    combine_kernel<<<cgrid, 512, CSMEM_BYTES>>>(b, out);
}

// round 17
// speedup vs baseline: 1.2074x; 1.2074x over previous
#include <cuda_runtime.h>
#include <cuda_fp16.h>
#include <cstdint>

#define MDIM 65536      // 4*128*128 input pixels
#define KDIM 256        // input channels
#define NDIM 2304       // 9 taps * 256 out channels

__device__ float g_z[(size_t)MDIM * NDIM];       // z = x @ B^T (604 MB)
__device__ __half g_Bh[(size_t)NDIM * KDIM];     // B[n=(t,co)][ci] fp16
__device__ __half g_xh[(size_t)MDIM * KDIM];     // x hi fp16
__device__ __half g_xl[(size_t)MDIM * KDIM];     // x residual fp16

__device__ __forceinline__ uint32_t smem_to_u32(const void* p) {
    uint32_t a;
    asm("{ .reg .u64 t; cvta.to.shared.u64 t, %1; cvt.u32.u64 %0, t; }" : "=r"(a) : "l"(p));
    return a;
}
__device__ __forceinline__ void cp_async16(uint32_t dst, const void* src) {
    asm volatile("cp.async.cg.shared.global [%0], [%1], 16;"
                 :: "r"(dst), "l"(__cvta_generic_to_global(src)));
}
// 16B copy with zero-fill when srcsz == 0 (ignore-src form)
__device__ __forceinline__ void cp_async16_z(uint32_t dst, const void* src, uint32_t srcsz) {
    asm volatile("cp.async.cg.shared.global [%0], [%1], 16, %2;"
                 :: "r"(dst), "l"(__cvta_generic_to_global(src)), "r"(srcsz));
}
#define CP_COMMIT() asm volatile("cp.async.commit_group;" ::: "memory")
#define CP_WAIT(N)  asm volatile("cp.async.wait_group %0;" :: "n"(N) : "memory")

#define LDMATRIX_X4(r0, r1, r2, r3, addr) \
    asm volatile("ldmatrix.sync.aligned.m8n8.x4.shared.b16 {%0,%1,%2,%3}, [%4];" \
                 : "=r"(r0), "=r"(r1), "=r"(r2), "=r"(r3) : "r"(addr))

__device__ __forceinline__ void mma16816(float* d, const uint32_t* a,
                                         uint32_t b0, uint32_t b1) {
    asm volatile(
        "mma.sync.aligned.m16n8k16.row.col.f32.f16.f16.f32 "
        "{%0,%1,%2,%3}, {%4,%5,%6,%7}, {%8,%9}, {%0,%1,%2,%3};"
        : "+f"(d[0]), "+f"(d[1]), "+f"(d[2]), "+f"(d[3])
        : "r"(a[0]), "r"(a[1]), "r"(a[2]), "r"(a[3]), "r"(b0), "r"(b1));
}

// FIR/phase coefficients A[r][jn][t], jn=j+1; l-index offset uses (2-jn).
__device__ constexpr float AT[2][3][3] = {
    { {0.00f, 0.00f, 0.25f},
      {0.25f, 0.75f, 0.75f},
      {0.75f, 0.25f, 0.00f} },
    { {0.00f, 0.25f, 0.75f},
      {0.75f, 0.75f, 0.25f},
      {0.25f, 0.00f, 0.00f} }
};

// ---------------------------------------------------------------------------
// Kernel 1a: B fp16  B[n=(t,co)][ci] = w[t][ci][co]
// ---------------------------------------------------------------------------
__global__ void prep_w_kernel(const float* __restrict__ w) {
    int o = blockIdx.x * 256 + threadIdx.x;
    int n  = o >> 8;
    int ci = o & 255;
    int tt = n >> 8;
    int co = n & 255;
    g_Bh[(size_t)n * KDIM + ci] = __float2half_rn(w[(tt * 256 + ci) * 256 + co]);
}

// ---------------------------------------------------------------------------
// Kernel 1b: fp16 hi/lo split of x (x = xh + xl, |xl| <= 2^-11 |x| roughly)
// ---------------------------------------------------------------------------
__global__ void prep_x_kernel(const float* __restrict__ x) {
    size_t i = ((size_t)blockIdx.x * 256 + threadIdx.x) * 4;
    const float4 v = *(const float4*)(x + i);
    __half2 h01 = __floats2half2_rn(v.x, v.y);
    __half2 h23 = __floats2half2_rn(v.z, v.w);
    float2 f01 = __half22float2(h01);
    float2 f23 = __half22float2(h23);
    __half2 l01 = __floats2half2_rn(v.x - f01.x, v.y - f01.y);
    __half2 l23 = __floats2half2_rn(v.z - f23.x, v.w - f23.y);
    *(uint2*)&g_xh[i] = make_uint2(*(uint32_t*)&h01, *(uint32_t*)&h23);
    *(uint2*)&g_xl[i] = make_uint2(*(uint32_t*)&l01, *(uint32_t*)&l23);
}

// ---------------------------------------------------------------------------
// Kernel 2: GEMM v4 — fp16 2-pass.  z = xh*Bh + xl*Bh  (xh*Bl term dropped;
// fp16's 11-bit mantissa keeps the omitted term ~2^-11 relative).
// BM=256, BN=128, 4 chunks of K=64; per chunk stage {Ah, Al, Bh}.
// 512 threads (8m x 2n warps, 32x64 tile), 2-stage cp.async, 1 CTA/SM.
// ---------------------------------------------------------------------------
#define LDSR 72
#define S_AH 0
#define S_AL 18432
#define S_BH 36864
#define STAGE_ELEMS 46080
#define GSMEM_BYTES (2 * STAGE_ELEMS * 2)   // 184320

__global__ __launch_bounds__(512, 1) void gemm_kernel() {
    extern __shared__ __half smem[];
    const uint32_t sb = smem_to_u32(smem);
    const int tid = threadIdx.x;
    const int lane = tid & 31;
    const int wid = tid >> 5;
    const int n0 = blockIdx.x * 128;
    const int m0 = blockIdx.y * 256;
    const int wm = (wid >> 1) * 32;          // 0..224
    const int wn = (wid & 1) * 64;

    auto load_chunk = [&](int stage, int kk) {
        const uint32_t base = sb + (uint32_t)(stage * STAGE_ELEMS * 2);
        // A tiles: 2 x 2048 16B-chunks (i = 0..7), B tile: 1024 (i = 8..9)
#pragma unroll
        for (int i = 0; i < 10; i++) {
            int c = i * 512 + tid;
            if (i < 8) {
                int t  = c >> 11;                 // 0 = hi, 1 = lo
                int r  = (c >> 3) & 255;
                int c8 = c & 7;
                const __half* src = (t ? g_xl : g_xh)
                                  + (size_t)(m0 + r) * KDIM + kk + c8 * 8;
                uint32_t dst = base + (uint32_t)(((t ? S_AL : S_AH)
                                  + r * LDSR + c8 * 8) * 2);
                cp_async16(dst, src);
            } else {
                int cc = c - 4096;                // 0..1023
                int r  = cc >> 3;                 // 0..127
                int c8 = cc & 7;
                const __half* src = g_Bh + (size_t)(n0 + r) * KDIM + kk + c8 * 8;
                uint32_t dst = base + (uint32_t)((S_BH + r * LDSR + c8 * 8) * 2);
                cp_async16(dst, src);
            }
        }
        CP_COMMIT();
    };

    float d[2][8][4];
#pragma unroll
    for (int i = 0; i < 2; i++)
#pragma unroll
        for (int j = 0; j < 8; j++)
#pragma unroll
            for (int q = 0; q < 4; q++) d[i][j][q] = 0.f;

    const int ar = (lane & 7) + ((lane >> 3) & 1) * 8;
    const int ac = (lane >> 4) * 8;
    const int br = (lane & 7) + ((lane >> 4) & 1) * 8;
    const int bc = ((lane >> 3) & 1) * 8;

    load_chunk(0, 0);

    for (int ch = 0; ch < 4; ch++) {
        CP_WAIT(0);
        __syncthreads();
        if (ch < 3) load_chunk((ch + 1) & 1, (ch + 1) * 64);

        const uint32_t st = sb + (uint32_t)((ch & 1) * STAGE_ELEMS * 2);
#pragma unroll
        for (int k16 = 0; k16 < 4; k16++) {
            const int kc = k16 * 16;
            uint32_t ah[2][4], al[2][4], bh[4][4];
#pragma unroll
            for (int mt = 0; mt < 2; mt++) {
                int r = wm + mt * 16 + ar;
                int c = kc + ac;
                LDMATRIX_X4(ah[mt][0], ah[mt][1], ah[mt][2], ah[mt][3],
                            st + (uint32_t)((S_AH + r * LDSR + c) * 2));
                LDMATRIX_X4(al[mt][0], al[mt][1], al[mt][2], al[mt][3],
                            st + (uint32_t)((S_AL + r * LDSR + c) * 2));
            }
#pragma unroll
            for (int nt = 0; nt < 4; nt++) {
                int rb = wn + nt * 16 + br;
                int cb = kc + bc;
                LDMATRIX_X4(bh[nt][0], bh[nt][1], bh[nt][2], bh[nt][3],
                            st + (uint32_t)((S_BH + rb * LDSR + cb) * 2));
            }
            // pass 1: xh * Bh
#pragma unroll
            for (int mt = 0; mt < 2; mt++)
#pragma unroll
                for (int nt = 0; nt < 4; nt++)
#pragma unroll
                    for (int h = 0; h < 2; h++)
                        mma16816(d[mt][nt * 2 + h], ah[mt], bh[nt][h * 2], bh[nt][h * 2 + 1]);
            // pass 2: xl * Bh
#pragma unroll
            for (int mt = 0; mt < 2; mt++)
#pragma unroll
                for (int nt = 0; nt < 4; nt++)
#pragma unroll
                    for (int h = 0; h < 2; h++)
                        mma16816(d[mt][nt * 2 + h], al[mt], bh[nt][h * 2], bh[nt][h * 2 + 1]);
        }
    }

#pragma unroll
    for (int mt = 0; mt < 2; mt++) {
        const int mrow = m0 + wm + mt * 16 + (lane >> 2);
#pragma unroll
        for (int j = 0; j < 8; j++) {
            const int ncol = n0 + wn + (j >> 1) * 16 + (j & 1) * 8 + (lane & 3) * 2;
            float* p0 = g_z + (size_t)mrow * NDIM + ncol;
            float* p1 = g_z + (size_t)(mrow + 8) * NDIM + ncol;
            *(float2*)p0 = make_float2(d[mt][j][0], d[mt][j][1]);
            *(float2*)p1 = make_float2(d[mt][j][2], d[mt][j][3]);
        }
    }
}

// ---------------------------------------------------------------------------
// Kernel 3: combine v4 — separable, l1-slice streamed, 2 CTAs/SM. (unchanged)
// ---------------------------------------------------------------------------
#define SS_FLOATS 15360
#define ZB_FLOATS (4 * 2880)
#define CSMEM_BYTES ((SS_FLOATS + ZB_FLOATS) * 4)   // 107520

__global__ __launch_bounds__(512) void combine_kernel(const float* __restrict__ bias,
                                                      float* __restrict__ out) {
    extern __shared__ float ss[];            // [10][8][6][32]
    float* zb = ss + SS_FLOATS;              // [4][90][32]
    const uint32_t zbb = smem_to_u32(zb);

    const int co0 = blockIdx.x * 32;
    const int T2  = blockIdx.y;
    const int bz  = blockIdx.z;
    const int b   = bz >> 4;
    const int T1  = bz & 15;
    const int u10 = T1 * 8, u20 = T2 * 8;
    const int tid = threadIdx.x;
    const int lane = tid & 31;
    const int warp = tid >> 5;

    auto load_pair = [&](int j) {
        const int sub = tid >> 3;
        const int qo  = (tid & 7) * 4;
#pragma unroll
        for (int pass = 0; pass < 3; pass++) {
            int c = pass * 64 + sub;
            if (c < 180) {
                int sl = (c >= 90) ? 1 : 0;
                int rem = c - sl * 90;
                int l2 = rem / 9;
                int t  = rem - l2 * 9;
                int l1 = 2 * j + sl;
                int u1 = u10 + l1 - 1;
                int u2 = u20 + l2 - 1;
                bool ok = ((unsigned)u1 < 128u) && ((unsigned)u2 < 128u);
                int cu1 = ok ? u1 : 0, cu2 = ok ? u2 : 0;
                const float* src = g_z + (size_t)((b * 128 + cu1) * 128 + cu2) * NDIM
                                       + t * 256 + co0 + qo;
                int slot = (2 * j + sl) & 3;
                cp_async16_z(zbb + (uint32_t)((slot * 90 + l2 * 9 + t) * 32 + qo) * 4,
                             src, ok ? 16u : 0u);
            }
        }
        CP_COMMIT();
    };

    load_pair(0);
    load_pair(1);

    const int p  = warp >> 3;
    const int c2 = warp & 7;

    for (int i = 0; i < 5; i++) {
        if (i < 4) { CP_WAIT(1); } else { CP_WAIT(0); }
        __syncthreads();

        {
            const int l1 = 2 * i + p;
            const float* zsl = zb + ((2 * i + p) & 3) * 2880;
            const float* zrow = zsl + c2 * 288 + lane;
            float acc[2][3] = {{0.f, 0.f, 0.f}, {0.f, 0.f, 0.f}};
#pragma unroll
            for (int jn = 0; jn < 3; jn++) {
                const int l2off = (2 - jn) * 288;
#pragma unroll
                for (int t2 = 0; t2 < 3; t2++) {
                    const float c0  = AT[0][jn][t2];
                    const float c1v = AT[1][jn][t2];
                    if (c0 == 0.f && c1v == 0.f) continue;
                    float zv0 = zrow[l2off + (0 * 3 + t2) * 32];
                    float zv1 = zrow[l2off + (1 * 3 + t2) * 32];
                    float zv2 = zrow[l2off + (2 * 3 + t2) * 32];
                    if (c0 != 0.f) {
                        acc[0][0] = fmaf(c0, zv0, acc[0][0]);
                        acc[0][1] = fmaf(c0, zv1, acc[0][1]);
                        acc[0][2] = fmaf(c0, zv2, acc[0][2]);
                    }
                    if (c1v != 0.f) {
                        acc[1][0] = fmaf(c1v, zv0, acc[1][0]);
                        acc[1][1] = fmaf(c1v, zv1, acc[1][1]);
                        acc[1][2] = fmaf(c1v, zv2, acc[1][2]);
                    }
                }
            }
            float* sp = ss + ((l1 * 8 + c2) * 6) * 32 + lane;
#pragma unroll
            for (int r2 = 0; r2 < 2; r2++)
#pragma unroll
                for (int t1 = 0; t1 < 3; t1++)
                    sp[(r2 * 3 + t1) * 32] = acc[r2][t1];
        }
        __syncthreads();
        if (i + 2 < 5) load_pair(i + 2);
    }

    const float bv = bias[co0 + lane];
#pragma unroll
    for (int i = 0; i < 4; i++) {
        const int g = warp + 16 * i;
        const int c1 = g >> 3;
        const int c2b = g & 7;
        const float* sp = ss + ((c1 * 8 + c2b) * 6) * 32 + lane;
        float o00 = 0.f, o01 = 0.f, o10 = 0.f, o11 = 0.f;
#pragma unroll
        for (int jn = 0; jn < 3; jn++) {
            const int l1off = (2 - jn) * 1536;
#pragma unroll
            for (int t1 = 0; t1 < 3; t1++) {
                const float c0  = AT[0][jn][t1];
                const float c1v = AT[1][jn][t1];
                if (c0 == 0.f && c1v == 0.f) continue;
                float s0 = sp[l1off + (0 * 3 + t1) * 32];
                float s1 = sp[l1off + (1 * 3 + t1) * 32];
                if (c0 != 0.f)  { o00 = fmaf(c0,  s0, o00); o01 = fmaf(c0,  s1, o01); }
                if (c1v != 0.f) { o10 = fmaf(c1v, s0, o10); o11 = fmaf(c1v, s1, o11); }
            }
        }
        const int o1 = 2 * (u10 + c1);
        const int o2 = 2 * (u20 + c2b);
        float* pp = out + (((size_t)(b * 256 + o1)) * 256 + o2) * 256 + co0 + lane;
        pp[0]           = o00 + bv;
        pp[256]         = o01 + bv;
        pp[65536]       = o10 + bv;
        pp[65536 + 256] = o11 + bv;
    }
}

// ---------------------------------------------------------------------------
extern "C" void kernel_launch(void* const* d_in, const int* in_sizes, int n_in,
                              void* d_out, int out_size) {
    const float* x = (const float*)d_in[0];   // [4,128,128,256]
    const float* w = (const float*)d_in[1];   // [3,3,256,256]
    const float* b = (const float*)d_in[2];   // [256]
    float* out = (float*)d_out;               // [4,256,256,256]

    prep_w_kernel<<<2304, 256>>>(w);
    prep_x_kernel<<<16384, 256>>>(x);

    cudaFuncSetAttribute(gemm_kernel,
                         cudaFuncAttributeMaxDynamicSharedMemorySize, GSMEM_BYTES);
    dim3 ggrid(NDIM / 128, MDIM / 256);       // (18, 256)
    gemm_kernel<<<ggrid, 512, GSMEM_BYTES>>>();

    cudaFuncSetAttribute(combine_kernel,
                         cudaFuncAttributeMaxDynamicSharedMemorySize, CSMEM_BYTES);
    dim3 cgrid(8, 16, 64);
    combine_kernel<<<cgrid, 512, CSMEM_BYTES>>>(b, out);
}